// round 2
// baseline (speedup 1.0000x reference)
#include <cuda_runtime.h>
#include <math.h>

#define H_ 200
#define W_ 352
#define HW_ (H_*W_)
#define CHW_ (64*HW_)

typedef unsigned long long ull;

// ---------------- scratch (static device memory; no allocations) ----------------
__device__ __align__(16) float g_agg[4*CHW_];   // agg = 0.5*(x0+message), per batch
__device__ __align__(16) float g_h  [CHW_];     // GRU hidden state
__device__ __align__(16) float g_rh [CHW_];     // reset * h
__device__ __align__(16) float g_u  [CHW_];     // update gate
// packed weights: for each ci, 32 channel-pairs x 9 taps as float2 (= 144 float4)
__device__ float4 g_wmsg  [128*144];
__device__ float4 g_wgates[2*192*144];
__device__ float4 g_wcan  [192*144];

// ---------------- helpers ----------------
__device__ __forceinline__ void fma2(ull& d, ull a, ull b) {
    asm("fma.rn.f32x2 %0,%1,%2,%0;" : "+l"(d) : "l"(a), "l"(b));
}

enum { MODE_MSG = 0, MODE_GATES = 1, MODE_CAN = 2 };

// Per-stage shared buffers: 2 input channels per stage.
// in4d: input rows duplicated as (v,v) pairs -> 6 rows x 20 float4 (80 floats = 40 ull pairs)
// w4:   144 float4 per ci = 32 pairs x 9 taps (float2 each)
struct SB2 {
    float4 in4d[2][6][20];
    float4 w4[2][144];
};

// ---------------- fused conv3x3 + epilogue ----------------
// Tile: 32 (W, lanes) x 4 (H, per-thread rows) pixels, 64 out channels
// (8 warps x 8 channels = 4 fp32x2 channel-pairs per warp-thread).
template<int C0, int C1, int C2, int MODE>
__global__ void __launch_bounds__(256, 2)
conv3x3_k(const float* __restrict__ xin, const float* __restrict__ bias,
          float* __restrict__ dout, int t)
{
    __shared__ SB2 sb[2];
    const int tid = threadIdx.x, lx = tid & 31, wq = tid >> 5;
    const int x0 = blockIdx.x * 32, y0 = blockIdx.y * 4;
    const int z  = blockIdx.z;

    const float *p0, *p1, *p2 = nullptr;
    const float4* wsrc;
    float* o0;
    const float* bptr = bias;
    if (MODE == MODE_MSG) {            // inputs: [x0_b, x1_b], out: agg_b
        p0 = xin + (size_t)z * CHW_;            // agent 0, batch z
        p1 = xin + (size_t)(4 + z) * CHW_;      // agent 1, batch z
        wsrc = g_wmsg;
        o0 = g_agg + (size_t)z * CHW_;
    } else if (MODE == MODE_GATES) {   // inputs: [x0_t, agg_t, h]; z=0 -> rh, z=1 -> u
        p0 = xin   + (size_t)t * CHW_;
        p1 = g_agg + (size_t)t * CHW_;
        p2 = g_h;
        wsrc = g_wgates + (size_t)z * (192*144);
        bptr = bias + z * 64;
        o0 = z ? g_u : g_rh;
    } else {                           // CAN: inputs: [x0_t, agg_t, rh]; out: h + dout[t]
        p0 = xin   + (size_t)t * CHW_;
        p1 = g_agg + (size_t)t * CHW_;
        p2 = g_rh;
        wsrc = g_wcan;
        o0 = g_h;
    }

    ull acc[4][4];
    #pragma unroll
    for (int p = 0; p < 4; p++)
        #pragma unroll
        for (int r = 0; r < 4; r++) acc[p][r] = 0ull;

    const int NST = (C0 + C1 + C2) / 2;   // 2 input channels per stage

    auto plane = [&](int ci) -> const float* {
        if (ci < C0) return p0 + (size_t)ci * HW_;
        if (C2 == 0 || ci < C0 + C1) return p1 + (size_t)(ci - C0) * HW_;
        return p2 + (size_t)(ci - C0 - C1) * HW_;
    };

    // staging registers (LDG issued before compute, STS after)
    float4 ra, rw0, rw1;

    auto gload = [&](int st) {
        const int ci0 = st * 2;
        if (tid < 120) {
            int cil = tid / 60, task = tid % 60;
            int rr = task / 10, q = task % 10;
            int yy = y0 - 1 + rr, cc = x0 - 4 + 4 * q;
            if ((unsigned)yy < (unsigned)H_ && (unsigned)cc < (unsigned)W_)
                ra = *(const float4*)(plane(ci0 + cil) + (size_t)yy * W_ + cc);
            else
                ra = make_float4(0.f, 0.f, 0.f, 0.f);
        }
        { // weight tasks 0..255
            int cil = tid / 144;                   // 0 for tid<144, 1 for 144..255
            rw0 = wsrc[(size_t)(ci0 + cil) * 144 + (tid - cil * 144)];
        }
        if (tid < 32)                              // weight tasks 256..287 (cil=1, idx 112..143)
            rw1 = wsrc[(size_t)(ci0 + 1) * 144 + 112 + tid];
    };
    auto sstore = [&](int buf) {
        if (tid < 120) {
            int cil = tid / 60, task = tid % 60;
            int rr = task / 10, q = task % 10;
            // duplicate each float into a (v,v) pair
            sb[buf].in4d[cil][rr][2 * q]     = make_float4(ra.x, ra.x, ra.y, ra.y);
            sb[buf].in4d[cil][rr][2 * q + 1] = make_float4(ra.z, ra.z, ra.w, ra.w);
        }
        {
            int cil = tid / 144;
            sb[buf].w4[cil][tid - cil * 144] = rw0;
        }
        if (tid < 32)
            sb[buf].w4[1][112 + tid] = rw1;
    };

    // prologue
    gload(0); sstore(0);
    __syncthreads();

    for (int st = 0; st < NST; st++) {
        const bool more = (st + 1 < NST);
        if (more) gload(st + 1);                   // LDG before compute

        const SB2& b = sb[st & 1];
        #pragma unroll
        for (int cil = 0; cil < 2; cil++) {
            ull iv[6][3];
            #pragma unroll
            for (int rr = 0; rr < 6; rr++) {
                const ull* rowp = (const ull*)&b.in4d[cil][rr][0];
                #pragma unroll
                for (int dx = 0; dx < 3; dx++)
                    iv[rr][dx] = rowp[lx + 3 + dx];
            }
            const ull* wp = ((const ull*)b.w4[cil]) + wq * 36;   // this warp's 4 pairs
            #pragma unroll
            for (int p = 0; p < 4; p++) {
                ull wk[9];
                #pragma unroll
                for (int k = 0; k < 9; k++) wk[k] = wp[p * 9 + k];
                #pragma unroll
                for (int dy = 0; dy < 3; dy++)
                    #pragma unroll
                    for (int dx = 0; dx < 3; dx++)
                        #pragma unroll
                        for (int r = 0; r < 4; r++)    // r innermost: 4 indep acc chains
                            fma2(acc[p][r], wk[dy * 3 + dx], iv[r + dy][dx]);
            }
        }
        if (more) sstore((st + 1) & 1);            // STS after compute
        __syncthreads();
    }

    // ---------------- epilogue ----------------
    const int xg = x0 + lx;
    #pragma unroll
    for (int p = 0; p < 4; p++) {
        int co = wq * 8 + 2 * p;
        float b0 = bptr[co], b1 = bptr[co + 1];
        #pragma unroll
        for (int r = 0; r < 4; r++) {
            float ax, ay;
            asm("mov.b64 {%0,%1},%2;" : "=f"(ax), "=f"(ay) : "l"(acc[p][r]));
            ax += b0; ay += b1;
            size_t off0 = (size_t)co * HW_ + (size_t)(y0 + r) * W_ + xg;
            size_t off1 = off0 + HW_;
            if (MODE == MODE_MSG) {
                o0[off0] = 0.5f * (p0[off0] + ax);
                o0[off1] = 0.5f * (p0[off1] + ay);
            } else if (MODE == MODE_GATES) {
                float s0 = 1.f / (1.f + __expf(-ax));
                float s1 = 1.f / (1.f + __expf(-ay));
                if (z == 0) { o0[off0] = s0 * g_h[off0]; o0[off1] = s1 * g_h[off1]; }
                else        { o0[off0] = s0;             o0[off1] = s1;             }
            } else {
                float c0 = __tanhf(ax), c1 = __tanhf(ay);
                float u0 = g_u[off0], u1 = g_u[off1];
                float h0 = g_h[off0], h1 = g_h[off1];
                float n0 = h0 + u0 * (c0 - h0);
                float n1 = h1 + u1 * (c1 - h1);
                g_h[off0] = n0; g_h[off1] = n1;
                float* ot = dout + (size_t)t * CHW_;
                ot[off0] = n0; ot[off1] = n1;
            }
        }
    }
}

// ---------------- weight repack: [co][ci][3][3] -> [ci][pair][tap] float2 ----------------
__global__ void repack_k(const float* __restrict__ mw, const float* __restrict__ gw,
                         const float* __restrict__ cw)
{
    int i = blockIdx.x * blockDim.x + threadIdx.x;
    if (i < 128 * 288) {                       // msg: Cout=64, Cin=128
        int k = i % 9, pr = (i / 9) & 31, ci = i / 288;
        ((float2*)g_wmsg)[i] = make_float2(mw[((2 * pr) * 128 + ci) * 9 + k],
                                           mw[((2 * pr + 1) * 128 + ci) * 9 + k]);
    }
    int j = i - 128 * 288;
    if (j >= 0 && j < 2 * 192 * 288) {         // gates: Cout=128 (2 halves), Cin=192
        int k = j % 9, pr = (j / 9) & 31, ci = (j / 288) % 192, zz = j / (192 * 288);
        int co = zz * 64 + 2 * pr;
        ((float2*)g_wgates)[j] = make_float2(gw[(co * 192 + ci) * 9 + k],
                                             gw[((co + 1) * 192 + ci) * 9 + k]);
    }
    int m = j - 2 * 192 * 288;
    if (m >= 0 && m < 192 * 288) {             // can: Cout=64, Cin=192
        int k = m % 9, pr = (m / 9) & 31, ci = m / 288;
        ((float2*)g_wcan)[m] = make_float2(cw[((2 * pr) * 192 + ci) * 9 + k],
                                           cw[((2 * pr + 1) * 192 + ci) * 9 + k]);
    }
}

__global__ void zero_h_k()
{
    int i = blockIdx.x * blockDim.x + threadIdx.x;
    int st = gridDim.x * blockDim.x;
    for (; i < CHW_; i += st) g_h[i] = 0.f;
}

// ---------------- launch ----------------
extern "C" void kernel_launch(void* const* d_in, const int* in_sizes, int n_in,
                              void* d_out, int out_size)
{
    const float* x  = (const float*)d_in[0];
    const float* mw = (const float*)d_in[1];
    const float* mb = (const float*)d_in[2];
    const float* gw = (const float*)d_in[3];
    const float* gb = (const float*)d_in[4];
    const float* cw = (const float*)d_in[5];
    const float* cb = (const float*)d_in[6];
    float* out = (float*)d_out;

    const int tot = 128 * 288 + 2 * 192 * 288 + 192 * 288;
    repack_k<<<(tot + 255) / 256, 256>>>(mw, gw, cw);
    zero_h_k<<<592, 256>>>();

    // message conv + agg, all 4 batches
    conv3x3_k<64, 64, 0, MODE_MSG><<<dim3(11, 50, 4), 256>>>(x, mb, nullptr, 0);

    // ConvGRU scan over the 4 "sequence" elements
    for (int t = 0; t < 4; t++) {
        conv3x3_k<64, 64, 64, MODE_GATES><<<dim3(11, 50, 2), 256>>>(x, gb, nullptr, t);
        conv3x3_k<64, 64, 64, MODE_CAN  ><<<dim3(11, 50, 1), 256>>>(x, cb, out, t);
    }
}

// round 5
// speedup vs baseline: 1.8382x; 1.8382x over previous
#include <cuda_runtime.h>
#include <cuda_bf16.h>
#include <math.h>
#include <stdint.h>

#define H_ 200
#define W_ 352
#define HW_ (H_*W_)
#define CHW_ (64*HW_)

// ---------------- scratch (static device memory; no allocations) ----------------
__device__ __align__(16) float g_agg[4*CHW_];
__device__ __align__(16) float g_h  [CHW_];
__device__ __align__(16) float g_rh [CHW_];
__device__ __align__(16) float g_u  [CHW_];
// bf16 split weights, layout [prec][chunk][co 64][j 64]  (lo plane at +NC*4096)
__device__ __align__(16) __nv_bfloat16 g_wb_msg[2*18*64*64];
__device__ __align__(16) __nv_bfloat16 g_wb_g0 [2*27*64*64];
__device__ __align__(16) __nv_bfloat16 g_wb_g1 [2*27*64*64];
__device__ __align__(16) __nv_bfloat16 g_wb_can[2*27*64*64];

// ---------------- helpers ----------------
__device__ __forceinline__ uint32_t smem_u32(const void* p) {
    uint32_t a;
    asm("{ .reg .u64 t; cvta.to.shared.u64 t, %1; cvt.u32.u64 %0, t; }" : "=r"(a) : "l"(p));
    return a;
}
#define SW128(o) ((o) ^ (((o) >> 3) & 0x70))

#define LDSM4(R, A) \
    asm volatile("ldmatrix.sync.aligned.m8n8.x4.shared.b16 {%0,%1,%2,%3}, [%4];" \
        : "=r"((R)[0]), "=r"((R)[1]), "=r"((R)[2]), "=r"((R)[3]) : "r"(A))

#define MMA16816(C, A, B0, B1) \
    asm volatile("mma.sync.aligned.m16n8k16.row.col.f32.bf16.bf16.f32 " \
        "{%0,%1,%2,%3},{%4,%5,%6,%7},{%8,%9},{%0,%1,%2,%3};" \
        : "+f"((C)[0]), "+f"((C)[1]), "+f"((C)[2]), "+f"((C)[3]) \
        : "r"((A)[0]), "r"((A)[1]), "r"((A)[2]), "r"((A)[3]), "r"(B0), "r"(B1))

enum { MODE_MSG = 0, MODE_GATES = 1, MODE_CAN = 2 };

// smem layout (dynamic):
//  [1024]         W[buf][prec][8KB]   weights  64 co x 128B rows, SW128
//  [33792]        X[buf][prec][16KB]  im2col   128 px x 128B rows, SW128
#define OFF_W 1024
#define OFF_X 33792
#define SMEM_TOTAL (33792 + 65536)

// ---------------- tensor-core conv3x3 (mma.sync bf16 3-pass split) ----------------
// Tile: M=64 out-channels x 128 pixels along W (x-tiles {0,128,224}); one H row.
// Tiles 1 and 2 overlap on x [224,256): bx=2 COMPUTES all 128 pixels but only
// WRITES pixels with local index >= 32 (global x >= 256) -- removes the
// read-modify-write race on g_h that broke round 4.
template<int CT, int MODE>
__global__ void __launch_bounds__(256, 2)
convmma_k(const float* __restrict__ xin, const float* __restrict__ bias,
          float* __restrict__ dout, int t)
{
    extern __shared__ char smem[];
    const uint32_t sbase = smem_u32(smem);
    const int tid = threadIdx.x, wid = tid >> 5, lid = tid & 31;
    const int bx = blockIdx.x, y0 = blockIdx.y, z = blockIdx.z;
    const int x0 = (bx == 2) ? 224 : bx * 128;
    const int pxmin = (bx == 2) ? 32 : 0;     // ownership threshold (local px)
    const int NC = 9 * CT / 64;
    const int GPT = CT / 64;

    const float* pg[3];
    const __nv_bfloat16* wb;
    const float* bptr = bias;
    float* o0;
    if (MODE == MODE_MSG) {
        pg[0] = xin + (size_t)z * CHW_;
        pg[1] = xin + (size_t)(4 + z) * CHW_;
        pg[2] = nullptr;
        wb = g_wb_msg;
        o0 = g_agg + (size_t)z * CHW_;
    } else if (MODE == MODE_GATES) {
        pg[0] = xin + (size_t)t * CHW_;
        pg[1] = g_agg + (size_t)t * CHW_;
        pg[2] = g_h;
        wb = z ? g_wb_g1 : g_wb_g0;
        bptr = bias + z * 64;
        o0 = z ? g_u : g_rh;
    } else {
        pg[0] = xin + (size_t)t * CHW_;
        pg[1] = g_agg + (size_t)t * CHW_;
        pg[2] = g_rh;
        wb = g_wb_can;
        o0 = g_h;
    }

    // lane constants for ldmatrix addressing
    const int r8 = lid & 7, seg = lid >> 3;
    const uint32_t arow = (uint32_t)(((seg & 1) * 8 + r8) * 128);
    const int akb = seg >> 1;
    const uint32_t brow = (uint32_t)((wid * 16 + (seg >> 1) * 8 + r8) * 128);
    const int bkh = seg & 1;

    float acc[4][2][4];
    #pragma unroll
    for (int mt = 0; mt < 4; mt++)
        #pragma unroll
        for (int nt = 0; nt < 2; nt++)
            #pragma unroll
            for (int i = 0; i < 4; i++) acc[mt][nt][i] = 0.f;

    // staging registers
    float rf[32];
    float4 wr[4];

    auto ldg_chunk = [&](int c) {
        const int tap = c / GPT, cig = c % GPT;
        const int dy = tap / 3, dx = tap % 3;
        const int srow = y0 + dy - 1;
        const bool vy = (unsigned)srow < (unsigned)H_;
        const float* sp = pg[cig] + (size_t)srow * W_;
        #pragma unroll
        for (int q = 0; q < 4; q++) {
            const int j0 = wid * 8 + q * 2;
            const float* s0 = sp + (size_t)j0 * HW_;
            const float* s1 = s0 + HW_;
            #pragma unroll
            for (int g = 0; g < 4; g++) {
                const int p = g * 32 + lid;
                const int x = x0 - 1 + dx + p;
                const bool v = vy && (unsigned)x < (unsigned)W_;
                rf[(q * 4 + g) * 2]     = v ? s0[x] : 0.f;
                rf[(q * 4 + g) * 2 + 1] = v ? s1[x] : 0.f;
            }
        }
        #pragma unroll
        for (int i = 0; i < 4; i++) {
            int t4 = tid + 256 * i;                 // 0..1023
            int prec = t4 >> 9, idx = t4 & 511;
            wr[i] = ((const float4*)wb)[(size_t)(prec ? (NC + c) : c) * 512 + idx];
        }
    };
    auto sts_chunk = [&](int c) {
        const int buf = c & 1;
        char* Xh = smem + OFF_X + buf * 32768;
        char* Xl = Xh + 16384;
        #pragma unroll
        for (int q = 0; q < 4; q++) {
            const int j0 = wid * 8 + q * 2;
            #pragma unroll
            for (int g = 0; g < 4; g++) {
                const int p = g * 32 + lid;
                float f0 = rf[(q * 4 + g) * 2];
                float f1 = rf[(q * 4 + g) * 2 + 1];
                __nv_bfloat16 h0 = __float2bfloat16(f0);
                __nv_bfloat16 h1 = __float2bfloat16(f1);
                __nv_bfloat16 l0 = __float2bfloat16(f0 - __bfloat162float(h0));
                __nv_bfloat16 l1 = __float2bfloat16(f1 - __bfloat162float(h1));
                uint32_t so = SW128((uint32_t)(p * 128 + j0 * 2));
                uint32_t hp = (uint32_t)__bfloat16_as_ushort(h0) |
                              ((uint32_t)__bfloat16_as_ushort(h1) << 16);
                uint32_t lp = (uint32_t)__bfloat16_as_ushort(l0) |
                              ((uint32_t)__bfloat16_as_ushort(l1) << 16);
                *(uint32_t*)(Xh + so) = hp;
                *(uint32_t*)(Xl + so) = lp;
            }
        }
        char* Wb = smem + OFF_W + buf * 16384;
        #pragma unroll
        for (int i = 0; i < 4; i++) {
            int t4 = tid + 256 * i;
            int prec = t4 >> 9, idx = t4 & 511;
            *(float4*)(Wb + prec * 8192 + SW128((uint32_t)(idx * 16))) = wr[i];
        }
    };

    // prologue
    ldg_chunk(0); sts_chunk(0);
    __syncthreads();

    for (int c = 0; c < NC; c++) {
        const bool more = (c + 1 < NC);
        if (more) ldg_chunk(c + 1);

        const int buf = c & 1;
        const uint32_t wH = sbase + OFF_W + buf * 16384;
        const uint32_t wL = wH + 8192;
        const uint32_t xH = sbase + OFF_X + buf * 32768;
        const uint32_t xL = xH + 16384;

        #pragma unroll
        for (int ks = 0; ks < 4; ks++) {
            const uint32_t aoff = arow + ((uint32_t)((ks * 2 + akb) ^ r8) << 4);
            const uint32_t boff = brow + ((uint32_t)((ks * 2 + bkh) ^ r8) << 4);
            uint32_t bh[4], bl[4];
            LDSM4(bh, xH + boff);
            LDSM4(bl, xL + boff);
            #pragma unroll
            for (int mt = 0; mt < 4; mt++) {
                uint32_t ah[4], al[4];
                LDSM4(ah, wH + mt * 2048 + aoff);
                MMA16816(acc[mt][0], ah, bh[0], bh[1]);
                MMA16816(acc[mt][1], ah, bh[2], bh[3]);
                MMA16816(acc[mt][0], ah, bl[0], bl[1]);
                MMA16816(acc[mt][1], ah, bl[2], bl[3]);
                LDSM4(al, wL + mt * 2048 + aoff);
                MMA16816(acc[mt][0], al, bh[0], bh[1]);
                MMA16816(acc[mt][1], al, bh[2], bh[3]);
            }
        }
        if (more) sts_chunk(c + 1);
        __syncthreads();
    }

    // ---------------- epilogue: acc (co x pixel) -> fused GRU math ----------------
    // Only the owning block writes a pixel (pxl >= pxmin) -> no cross-block race.
    const int g = lid >> 2, tg = lid & 3;
    #pragma unroll
    for (int mt = 0; mt < 4; mt++) {
        #pragma unroll
        for (int nt = 0; nt < 2; nt++) {
            const int pxl = wid * 16 + nt * 8 + tg * 2;
            if (pxl < pxmin) continue;
            const size_t pbase = (size_t)y0 * W_ + x0 + pxl;
            #pragma unroll
            for (int hrow = 0; hrow < 2; hrow++) {
                const int co = mt * 16 + g + hrow * 8;
                const float bv = bptr[co];
                float d0 = acc[mt][nt][hrow * 2]     + bv;
                float d1 = acc[mt][nt][hrow * 2 + 1] + bv;
                const size_t off = (size_t)co * HW_ + pbase;
                if (MODE == MODE_MSG) {
                    float2 xv = *(const float2*)(pg[0] + off);
                    float2 ov = make_float2(0.5f * (xv.x + d0), 0.5f * (xv.y + d1));
                    *(float2*)(o0 + off) = ov;
                } else if (MODE == MODE_GATES) {
                    float s0 = 1.f / (1.f + __expf(-d0));
                    float s1 = 1.f / (1.f + __expf(-d1));
                    float2 ov;
                    if (z == 0) {
                        float2 hv = *(const float2*)(g_h + off);
                        ov = make_float2(s0 * hv.x, s1 * hv.y);
                    } else ov = make_float2(s0, s1);
                    *(float2*)(o0 + off) = ov;
                } else {
                    float c0 = tanhf(d0), c1 = tanhf(d1);
                    float2 uv = *(const float2*)(g_u + off);
                    float2 hv = *(const float2*)(g_h + off);
                    float n0 = hv.x + uv.x * (c0 - hv.x);
                    float n1 = hv.y + uv.y * (c1 - hv.y);
                    *(float2*)(g_h + off) = make_float2(n0, n1);
                    *(float2*)(dout + (size_t)t * CHW_ + off) = make_float2(n0, n1);
                }
            }
        }
    }
}

// ---------------- weight split+repack: OIHW fp32 -> [prec][chunk][co][j] bf16 ----------------
__global__ void repack_k(const float* __restrict__ mw, const float* __restrict__ gw,
                         const float* __restrict__ cw)
{
    int i = blockIdx.x * blockDim.x + threadIdx.x;
    const int S_MSG = 18 * 4096, S_G = 27 * 4096;
    if (i >= S_MSG + 3 * S_G) return;

    const float* src; __nv_bfloat16* dst; int CT, NCc, coadd = 0;
    if (i < S_MSG)                       { src = mw; dst = g_wb_msg; CT = 128; NCc = 18; }
    else if ((i -= S_MSG) < S_G)         { src = gw; dst = g_wb_g0;  CT = 192; NCc = 27; }
    else if ((i -= S_G) < S_G)           { src = gw; dst = g_wb_g1;  CT = 192; NCc = 27; coadd = 64; }
    else                                 { i -= S_G; src = cw; dst = g_wb_can; CT = 192; NCc = 27; }

    int c = i >> 12, rr = i & 4095, co = rr >> 6, j = rr & 63;
    int gpt = CT / 64;
    int tap = c / gpt, cig = c % gpt;
    int dy = tap / 3, dx = tap % 3, ci = cig * 64 + j;
    float v = src[(((size_t)(co + coadd) * CT + ci) * 3 + dy) * 3 + dx];
    __nv_bfloat16 h = __float2bfloat16(v);
    dst[i] = h;
    dst[(size_t)NCc * 4096 + i] = __float2bfloat16(v - __bfloat162float(h));
}

__global__ void zero_h_k()
{
    int i = blockIdx.x * blockDim.x + threadIdx.x;
    int st = gridDim.x * blockDim.x;
    for (; i < CHW_; i += st) g_h[i] = 0.f;
}

// ---------------- launch ----------------
extern "C" void kernel_launch(void* const* d_in, const int* in_sizes, int n_in,
                              void* d_out, int out_size)
{
    const float* x  = (const float*)d_in[0];
    const float* mw = (const float*)d_in[1];
    const float* mb = (const float*)d_in[2];
    const float* gw = (const float*)d_in[3];
    const float* gb = (const float*)d_in[4];
    const float* cw = (const float*)d_in[5];
    const float* cb = (const float*)d_in[6];
    float* out = (float*)d_out;

    cudaFuncSetAttribute(convmma_k<128, MODE_MSG>,   cudaFuncAttributeMaxDynamicSharedMemorySize, SMEM_TOTAL);
    cudaFuncSetAttribute(convmma_k<192, MODE_GATES>, cudaFuncAttributeMaxDynamicSharedMemorySize, SMEM_TOTAL);
    cudaFuncSetAttribute(convmma_k<192, MODE_CAN>,   cudaFuncAttributeMaxDynamicSharedMemorySize, SMEM_TOTAL);

    const int tot = 18 * 4096 + 3 * 27 * 4096;
    repack_k<<<(tot + 255) / 256, 256>>>(mw, gw, cw);
    zero_h_k<<<592, 256>>>();

    // message conv + agg, all 4 batches
    convmma_k<128, MODE_MSG><<<dim3(3, 200, 4), 256, SMEM_TOTAL>>>(x, mb, nullptr, 0);

    // ConvGRU scan over the 4 "sequence" elements
    for (int t = 0; t < 4; t++) {
        convmma_k<192, MODE_GATES><<<dim3(3, 200, 2), 256, SMEM_TOTAL>>>(x, gb, nullptr, t);
        convmma_k<192, MODE_CAN  ><<<dim3(3, 200, 1), 256, SMEM_TOTAL>>>(x, cb, out, t);
    }
}

// round 6
// speedup vs baseline: 2.3003x; 1.2514x over previous
#include <cuda_runtime.h>
#include <cuda_fp16.h>
#include <math.h>
#include <stdint.h>

#define H_ 200
#define W_ 352
#define HW_ (H_*W_)
#define CHW_ (64*HW_)

// ---------------- scratch (static device memory; no allocations) ----------------
__device__ __align__(16) float g_agg[4*CHW_];
__device__ __align__(16) float g_h  [CHW_];
__device__ __align__(16) float g_rh [CHW_];
__device__ __align__(16) float g_u  [CHW_];
// fp16 weights, layout [chunk][co 64][j 64]
__device__ __align__(16) __half g_wh_msg[18*64*64];
__device__ __align__(16) __half g_wh_g0 [27*64*64];
__device__ __align__(16) __half g_wh_g1 [27*64*64];
__device__ __align__(16) __half g_wh_can[27*64*64];

// ---------------- helpers ----------------
__device__ __forceinline__ uint32_t smem_u32(const void* p) {
    uint32_t a;
    asm("{ .reg .u64 t; cvta.to.shared.u64 t, %1; cvt.u32.u64 %0, t; }" : "=r"(a) : "l"(p));
    return a;
}
#define SW128(o) ((o) ^ (((o) >> 3) & 0x70))

#define LDSM4(R, A) \
    asm volatile("ldmatrix.sync.aligned.m8n8.x4.shared.b16 {%0,%1,%2,%3}, [%4];" \
        : "=r"((R)[0]), "=r"((R)[1]), "=r"((R)[2]), "=r"((R)[3]) : "r"(A))

#define MMA16816H(C, A, B0, B1) \
    asm volatile("mma.sync.aligned.m16n8k16.row.col.f32.f16.f16.f32 " \
        "{%0,%1,%2,%3},{%4,%5,%6,%7},{%8,%9},{%0,%1,%2,%3};" \
        : "+f"((C)[0]), "+f"((C)[1]), "+f"((C)[2]), "+f"((C)[3]) \
        : "r"((A)[0]), "r"((A)[1]), "r"((A)[2]), "r"((A)[3]), "r"(B0), "r"(B1))

enum { MODE_MSG = 0, MODE_GATES = 1, MODE_CAN = 2 };

// smem layout (dynamic):
//  [1024]   W[buf]        8KB each   (64 co x 128B rows, SW128, fp16)
//  [17408]  X[buf][prec]  16KB each  (128 px x 128B rows, SW128; hi, lo fp16)
#define OFF_W 1024
#define OFF_X 17408
#define SMEM_TOTAL (17408 + 65536)

// ---------------- tensor-core conv3x3 (mma.sync fp16, pixel hi/lo 2-pass) ----------------
// Tile: M=64 out-channels x 128 pixels along W (x-tiles {0,128,224}); one H row.
// Tiles 1 and 2 overlap on x [224,256): bx=2 computes all, writes only px >= 32.
template<int CT, int MODE>
__global__ void __launch_bounds__(256, 2)
convmma_k(const float* __restrict__ xin, const float* __restrict__ bias,
          float* __restrict__ dout, int t)
{
    extern __shared__ char smem[];
    const uint32_t sbase = smem_u32(smem);
    const int tid = threadIdx.x, wid = tid >> 5, lid = tid & 31;
    const int bx = blockIdx.x, y0 = blockIdx.y, z = blockIdx.z;
    const int x0 = (bx == 2) ? 224 : bx * 128;
    const int pxmin = (bx == 2) ? 32 : 0;
    const int NC = 9 * CT / 64;
    const int GPT = CT / 64;

    const float* pg[3];
    const __half* wb;
    const float* bptr = bias;
    float* o0;
    if (MODE == MODE_MSG) {
        pg[0] = xin + (size_t)z * CHW_;
        pg[1] = xin + (size_t)(4 + z) * CHW_;
        pg[2] = nullptr;
        wb = g_wh_msg;
        o0 = g_agg + (size_t)z * CHW_;
    } else if (MODE == MODE_GATES) {
        pg[0] = xin + (size_t)t * CHW_;
        pg[1] = g_agg + (size_t)t * CHW_;
        pg[2] = g_h;
        wb = z ? g_wh_g1 : g_wh_g0;
        bptr = bias + z * 64;
        o0 = z ? g_u : g_rh;
    } else {
        pg[0] = xin + (size_t)t * CHW_;
        pg[1] = g_agg + (size_t)t * CHW_;
        pg[2] = g_rh;
        wb = g_wh_can;
        o0 = g_h;
    }

    // lane constants for ldmatrix addressing
    const int r8 = lid & 7, seg = lid >> 3;
    const uint32_t arow = (uint32_t)(((seg & 1) * 8 + r8) * 128);
    const int akb = seg >> 1;
    const uint32_t brow = (uint32_t)((wid * 16 + (seg >> 1) * 8 + r8) * 128);
    const int bkh = seg & 1;

    float acc[4][2][4];
    #pragma unroll
    for (int mt = 0; mt < 4; mt++)
        #pragma unroll
        for (int nt = 0; nt < 2; nt++)
            #pragma unroll
            for (int i = 0; i < 4; i++) acc[mt][nt][i] = 0.f;

    // staging registers
    float rf[32];
    float4 wr[2];

    auto ldg_chunk = [&](int c) {
        const int tap = c / GPT, cig = c % GPT;
        const int dy = tap / 3, dx = tap % 3;
        const int srow = y0 + dy - 1;
        const bool vy = (unsigned)srow < (unsigned)H_;
        const float* sp = pg[cig] + (size_t)srow * W_;
        #pragma unroll
        for (int q = 0; q < 4; q++) {
            const int j0 = wid * 8 + q * 2;
            const float* s0 = sp + (size_t)j0 * HW_;
            const float* s1 = s0 + HW_;
            #pragma unroll
            for (int g = 0; g < 4; g++) {
                const int p = g * 32 + lid;
                const int x = x0 - 1 + dx + p;
                const bool v = vy && (unsigned)x < (unsigned)W_;
                rf[(q * 4 + g) * 2]     = v ? s0[x] : 0.f;
                rf[(q * 4 + g) * 2 + 1] = v ? s1[x] : 0.f;
            }
        }
        #pragma unroll
        for (int i = 0; i < 2; i++) {
            int idx = tid + 256 * i;                // 0..511
            wr[i] = ((const float4*)wb)[(size_t)c * 512 + idx];
        }
    };
    auto sts_chunk = [&](int c) {
        const int buf = c & 1;
        char* Xh = smem + OFF_X + buf * 32768;
        char* Xl = Xh + 16384;
        #pragma unroll
        for (int q = 0; q < 4; q++) {
            const int j0 = wid * 8 + q * 2;
            #pragma unroll
            for (int g = 0; g < 4; g++) {
                const int p = g * 32 + lid;
                float f0 = rf[(q * 4 + g) * 2];
                float f1 = rf[(q * 4 + g) * 2 + 1];
                __half h0 = __float2half(f0);
                __half h1 = __float2half(f1);
                __half l0 = __float2half(f0 - __half2float(h0));
                __half l1 = __float2half(f1 - __half2float(h1));
                uint32_t so = SW128((uint32_t)(p * 128 + j0 * 2));
                uint32_t hp = (uint32_t)__half_as_ushort(h0) |
                              ((uint32_t)__half_as_ushort(h1) << 16);
                uint32_t lp = (uint32_t)__half_as_ushort(l0) |
                              ((uint32_t)__half_as_ushort(l1) << 16);
                *(uint32_t*)(Xh + so) = hp;
                *(uint32_t*)(Xl + so) = lp;
            }
        }
        char* Wb = smem + OFF_W + buf * 8192;
        #pragma unroll
        for (int i = 0; i < 2; i++) {
            int idx = tid + 256 * i;
            *(float4*)(Wb + SW128((uint32_t)(idx * 16))) = wr[i];
        }
    };

    // prologue
    ldg_chunk(0); sts_chunk(0);
    __syncthreads();

    for (int c = 0; c < NC; c++) {
        const bool more = (c + 1 < NC);
        if (more) ldg_chunk(c + 1);

        const int buf = c & 1;
        const uint32_t wH = sbase + OFF_W + buf * 8192;
        const uint32_t xH = sbase + OFF_X + buf * 32768;
        const uint32_t xL = xH + 16384;

        #pragma unroll
        for (int ks = 0; ks < 4; ks++) {
            const uint32_t aoff = arow + ((uint32_t)((ks * 2 + akb) ^ r8) << 4);
            const uint32_t boff = brow + ((uint32_t)((ks * 2 + bkh) ^ r8) << 4);
            uint32_t bh[4], bl[4];
            LDSM4(bh, xH + boff);
            LDSM4(bl, xL + boff);
            #pragma unroll
            for (int mt = 0; mt < 4; mt++) {
                uint32_t a[4];
                LDSM4(a, wH + mt * 2048 + aoff);
                MMA16816H(acc[mt][0], a, bh[0], bh[1]);
                MMA16816H(acc[mt][1], a, bh[2], bh[3]);
                MMA16816H(acc[mt][0], a, bl[0], bl[1]);
                MMA16816H(acc[mt][1], a, bl[2], bl[3]);
            }
        }
        if (more) sts_chunk(c + 1);
        __syncthreads();
    }

    // ---------------- epilogue: acc (co x pixel) -> fused GRU math ----------------
    const int g = lid >> 2, tg = lid & 3;
    #pragma unroll
    for (int mt = 0; mt < 4; mt++) {
        #pragma unroll
        for (int nt = 0; nt < 2; nt++) {
            const int pxl = wid * 16 + nt * 8 + tg * 2;
            if (pxl < pxmin) continue;
            const size_t pbase = (size_t)y0 * W_ + x0 + pxl;
            #pragma unroll
            for (int hrow = 0; hrow < 2; hrow++) {
                const int co = mt * 16 + g + hrow * 8;
                const float bv = bptr[co];
                float d0 = acc[mt][nt][hrow * 2]     + bv;
                float d1 = acc[mt][nt][hrow * 2 + 1] + bv;
                const size_t off = (size_t)co * HW_ + pbase;
                if (MODE == MODE_MSG) {
                    float2 xv = *(const float2*)(pg[0] + off);
                    float2 ov = make_float2(0.5f * (xv.x + d0), 0.5f * (xv.y + d1));
                    *(float2*)(o0 + off) = ov;
                } else if (MODE == MODE_GATES) {
                    float s0 = 1.f / (1.f + __expf(-d0));
                    float s1 = 1.f / (1.f + __expf(-d1));
                    float2 ov;
                    if (z == 0) {
                        float2 hv = *(const float2*)(g_h + off);
                        ov = make_float2(s0 * hv.x, s1 * hv.y);
                    } else ov = make_float2(s0, s1);
                    *(float2*)(o0 + off) = ov;
                } else {
                    float c0 = tanhf(d0), c1 = tanhf(d1);
                    float2 uv = *(const float2*)(g_u + off);
                    float2 hv = *(const float2*)(g_h + off);
                    float n0 = hv.x + uv.x * (c0 - hv.x);
                    float n1 = hv.y + uv.y * (c1 - hv.y);
                    *(float2*)(g_h + off) = make_float2(n0, n1);
                    *(float2*)(dout + (size_t)t * CHW_ + off) = make_float2(n0, n1);
                }
            }
        }
    }
}

// ---------------- weight repack: OIHW fp32 -> [chunk][co][j] fp16 ----------------
__global__ void repack_k(const float* __restrict__ mw, const float* __restrict__ gw,
                         const float* __restrict__ cw)
{
    int i = blockIdx.x * blockDim.x + threadIdx.x;
    const int S_MSG = 18 * 4096, S_G = 27 * 4096;
    if (i >= S_MSG + 3 * S_G) return;

    const float* src; __half* dst; int CT, coadd = 0;
    if (i < S_MSG)                       { src = mw; dst = g_wh_msg; CT = 128; }
    else if ((i -= S_MSG) < S_G)         { src = gw; dst = g_wh_g0;  CT = 192; }
    else if ((i -= S_G) < S_G)           { src = gw; dst = g_wh_g1;  CT = 192; coadd = 64; }
    else                                 { i -= S_G; src = cw; dst = g_wh_can; CT = 192; }

    int c = i >> 12, rr = i & 4095, co = rr >> 6, j = rr & 63;
    int gpt = CT / 64;
    int tap = c / gpt, cig = c % gpt;
    int dy = tap / 3, dx = tap % 3, ci = cig * 64 + j;
    float v = src[(((size_t)(co + coadd) * CT + ci) * 3 + dy) * 3 + dx];
    dst[i] = __float2half(v);
}

__global__ void zero_h_k()
{
    int i = blockIdx.x * blockDim.x + threadIdx.x;
    int st = gridDim.x * blockDim.x;
    for (; i < CHW_; i += st) g_h[i] = 0.f;
}

// ---------------- launch ----------------
extern "C" void kernel_launch(void* const* d_in, const int* in_sizes, int n_in,
                              void* d_out, int out_size)
{
    const float* x  = (const float*)d_in[0];
    const float* mw = (const float*)d_in[1];
    const float* mb = (const float*)d_in[2];
    const float* gw = (const float*)d_in[3];
    const float* gb = (const float*)d_in[4];
    const float* cw = (const float*)d_in[5];
    const float* cb = (const float*)d_in[6];
    float* out = (float*)d_out;

    cudaFuncSetAttribute(convmma_k<128, MODE_MSG>,   cudaFuncAttributeMaxDynamicSharedMemorySize, SMEM_TOTAL);
    cudaFuncSetAttribute(convmma_k<192, MODE_GATES>, cudaFuncAttributeMaxDynamicSharedMemorySize, SMEM_TOTAL);
    cudaFuncSetAttribute(convmma_k<192, MODE_CAN>,   cudaFuncAttributeMaxDynamicSharedMemorySize, SMEM_TOTAL);

    const int tot = 18 * 4096 + 3 * 27 * 4096;
    repack_k<<<(tot + 255) / 256, 256>>>(mw, gw, cw);
    zero_h_k<<<592, 256>>>();

    // message conv + agg, all 4 batches
    convmma_k<128, MODE_MSG><<<dim3(3, 200, 4), 256, SMEM_TOTAL>>>(x, mb, nullptr, 0);

    // ConvGRU scan over the 4 "sequence" elements
    for (int t = 0; t < 4; t++) {
        convmma_k<192, MODE_GATES><<<dim3(3, 200, 2), 256, SMEM_TOTAL>>>(x, gb, nullptr, t);
        convmma_k<192, MODE_CAN  ><<<dim3(3, 200, 1), 256, SMEM_TOTAL>>>(x, cb, out, t);
    }
}

// round 8
// speedup vs baseline: 3.1533x; 1.3708x over previous
#include <cuda_runtime.h>
#include <cuda_fp16.h>
#include <math.h>
#include <stdint.h>

#define H_ 200
#define W_ 352
#define HW_ (H_*W_)
#define CHW_ (64*HW_)

// ---------------- scratch (static device memory; no allocations) ----------------
__device__ __align__(16) float g_agg[4*CHW_];
__device__ __align__(16) float g_h  [CHW_];
__device__ __align__(16) float g_rh [CHW_];
__device__ __align__(16) float g_u  [CHW_];
// fp16 weights, layout [chunk][co 64][j 64]
__device__ __align__(16) __half g_wh_msg[18*64*64];
__device__ __align__(16) __half g_wh_g0 [27*64*64];
__device__ __align__(16) __half g_wh_g1 [27*64*64];
__device__ __align__(16) __half g_wh_can[27*64*64];

// ---------------- helpers ----------------
__device__ __forceinline__ uint32_t smem_u32(const void* p) {
    uint32_t a;
    asm("{ .reg .u64 t; cvta.to.shared.u64 t, %1; cvt.u32.u64 %0, t; }" : "=r"(a) : "l"(p));
    return a;
}
#define SW128(o) ((o) ^ (((o) >> 3) & 0x70))

#define LDSM4(R, A) \
    asm volatile("ldmatrix.sync.aligned.m8n8.x4.shared.b16 {%0,%1,%2,%3}, [%4];" \
        : "=r"((R)[0]), "=r"((R)[1]), "=r"((R)[2]), "=r"((R)[3]) : "r"(A))

#define MMA16816H(C, A, B0, B1) \
    asm volatile("mma.sync.aligned.m16n8k16.row.col.f32.f16.f16.f32 " \
        "{%0,%1,%2,%3},{%4,%5,%6,%7},{%8,%9},{%0,%1,%2,%3};" \
        : "+f"((C)[0]), "+f"((C)[1]), "+f"((C)[2]), "+f"((C)[3]) \
        : "r"((A)[0]), "r"((A)[1]), "r"((A)[2]), "r"((A)[3]), "r"(B0), "r"(B1))

enum { MODE_MSG = 0, MODE_GATES = 1, MODE_CAN = 2 };

// smem layout (dynamic):
//  [1024]   W[buf]        8KB each   (64 co x 128B rows, SW128, fp16)
//  [17408]  X[buf][prec]  16KB each  (128 px x 128B rows, SW128; hi, lo fp16)
#define OFF_W 1024
#define OFF_X 17408
#define SMEM_TOTAL (17408 + 65536)

// ---------------- tensor-core conv3x3 (mma.sync fp16, pixel hi/lo 2-pass) ----------------
// Tile: M=64 out-channels x 128 pixels along W (x-tiles {0,128,224}); one H row.
// Tiles 1 and 2 overlap on x [224,256): bx=2 computes all, writes only px >= 32.
// Staging: each thread owns pixel p = tid&127 and 4 ci-octets -> STS.128,
// conflict-free under SW128 (vs 4-way-conflicted STS.32 in round 6).
template<int CT, int MODE>
__global__ void __launch_bounds__(256, 2)
convmma_k(const float* __restrict__ xin, const float* __restrict__ bias,
          float* __restrict__ dout, int t)
{
    extern __shared__ char smem[];
    const uint32_t sbase = smem_u32(smem);
    const int tid = threadIdx.x, wid = tid >> 5, lid = tid & 31;
    const int bx = blockIdx.x, y0 = blockIdx.y, z = blockIdx.z;
    const int x0 = (bx == 2) ? 224 : bx * 128;
    const int pxmin = (bx == 2) ? 32 : 0;
    const int NC = 9 * CT / 64;
    const int GPT = CT / 64;

    const float* pg[3];
    const __half* wb;
    const float* bptr = bias;
    float* o0;
    if (MODE == MODE_MSG) {
        pg[0] = xin + (size_t)z * CHW_;
        pg[1] = xin + (size_t)(4 + z) * CHW_;
        pg[2] = nullptr;
        wb = g_wh_msg;
        o0 = g_agg + (size_t)z * CHW_;
    } else if (MODE == MODE_GATES) {
        pg[0] = xin + (size_t)t * CHW_;
        pg[1] = g_agg + (size_t)t * CHW_;
        pg[2] = g_h;
        wb = z ? g_wh_g1 : g_wh_g0;
        bptr = bias + z * 64;
        o0 = z ? g_u : g_rh;
    } else {
        pg[0] = xin + (size_t)t * CHW_;
        pg[1] = g_agg + (size_t)t * CHW_;
        pg[2] = g_rh;
        wb = g_wh_can;
        o0 = g_h;
    }

    // lane constants for ldmatrix addressing
    const int r8 = lid & 7, seg = lid >> 3;
    const uint32_t arow = (uint32_t)(((seg & 1) * 8 + r8) * 128);
    const int akb = seg >> 1;
    const uint32_t brow = (uint32_t)((wid * 16 + (seg >> 1) * 8 + r8) * 128);
    const int bkh = seg & 1;

    // staging constants (im2col fill)
    const int sp_px = tid & 127;            // pixel this thread stages
    const int sp_jc0 = tid >> 7;            // first ci-octet (0 or 1)

    float acc[4][2][4];
    #pragma unroll
    for (int mt = 0; mt < 4; mt++)
        #pragma unroll
        for (int nt = 0; nt < 2; nt++)
            #pragma unroll
            for (int i = 0; i < 4; i++) acc[mt][nt][i] = 0.f;

    // staging registers
    float rf[32];
    float4 wr[2];

    auto ldg_chunk = [&](int c) {
        const int tap = c / GPT, cig = c % GPT;
        const int dy = tap / 3, dx = tap % 3;
        const int srow = y0 + dy - 1;
        const bool vy = (unsigned)srow < (unsigned)H_;
        const int x = x0 - 1 + dx + sp_px;
        const bool v = vy && (unsigned)x < (unsigned)W_;
        const float* sp = pg[cig] + (size_t)srow * W_ + x;
        #pragma unroll
        for (int i = 0; i < 4; i++) {
            const int jc = sp_jc0 + 2 * i;          // ci-octet 0..7
            const float* s = sp + (size_t)(jc * 8) * HW_;
            #pragma unroll
            for (int k = 0; k < 8; k++)
                rf[i * 8 + k] = v ? s[(size_t)k * HW_] : 0.f;
        }
        #pragma unroll
        for (int i = 0; i < 2; i++) {
            int idx = tid + 256 * i;                // 0..511
            wr[i] = ((const float4*)wb)[(size_t)c * 512 + idx];
        }
    };
    auto sts_chunk = [&](int c) {
        const int buf = c & 1;
        char* Xh = smem + OFF_X + buf * 32768;
        char* Xl = Xh + 16384;
        #pragma unroll
        for (int i = 0; i < 4; i++) {
            const int jc = sp_jc0 + 2 * i;
            uint32_t hp[4], lp[4];
            #pragma unroll
            for (int k2 = 0; k2 < 4; k2++) {
                float f0 = rf[i * 8 + k2 * 2];
                float f1 = rf[i * 8 + k2 * 2 + 1];
                __half2 h2 = __floats2half2_rn(f0, f1);
                float2 hf = __half22float2(h2);
                __half2 l2 = __floats2half2_rn(f0 - hf.x, f1 - hf.y);
                hp[k2] = *(uint32_t*)&h2;
                lp[k2] = *(uint32_t*)&l2;
            }
            uint32_t so = SW128((uint32_t)(sp_px * 128 + jc * 16));
            *(uint4*)(Xh + so) = make_uint4(hp[0], hp[1], hp[2], hp[3]);
            *(uint4*)(Xl + so) = make_uint4(lp[0], lp[1], lp[2], lp[3]);
        }
        char* Wb = smem + OFF_W + buf * 8192;
        #pragma unroll
        for (int i = 0; i < 2; i++) {
            int idx = tid + 256 * i;
            *(float4*)(Wb + SW128((uint32_t)(idx * 16))) = wr[i];
        }
    };

    // prologue
    ldg_chunk(0); sts_chunk(0);
    __syncthreads();

    for (int c = 0; c < NC; c++) {
        const bool more = (c + 1 < NC);
        if (more) ldg_chunk(c + 1);

        const int buf = c & 1;
        const uint32_t wH = sbase + OFF_W + buf * 8192;
        const uint32_t xH = sbase + OFF_X + buf * 32768;
        const uint32_t xL = xH + 16384;

        #pragma unroll
        for (int ks = 0; ks < 4; ks++) {
            const uint32_t aoff = arow + ((uint32_t)((ks * 2 + akb) ^ r8) << 4);
            const uint32_t boff = brow + ((uint32_t)((ks * 2 + bkh) ^ r8) << 4);
            uint32_t bh[4], bl[4];
            LDSM4(bh, xH + boff);
            LDSM4(bl, xL + boff);
            #pragma unroll
            for (int mt = 0; mt < 4; mt++) {
                uint32_t a[4];
                LDSM4(a, wH + mt * 2048 + aoff);
                MMA16816H(acc[mt][0], a, bh[0], bh[1]);
                MMA16816H(acc[mt][1], a, bh[2], bh[3]);
                MMA16816H(acc[mt][0], a, bl[0], bl[1]);
                MMA16816H(acc[mt][1], a, bl[2], bl[3]);
            }
        }
        if (more) sts_chunk(c + 1);
        __syncthreads();
    }

    // ---------------- epilogue: acc (co x pixel) -> fused GRU math ----------------
    const int g = lid >> 2, tg = lid & 3;
    #pragma unroll
    for (int mt = 0; mt < 4; mt++) {
        #pragma unroll
        for (int nt = 0; nt < 2; nt++) {
            const int pxl = wid * 16 + nt * 8 + tg * 2;
            if (pxl < pxmin) continue;
            const size_t pbase = (size_t)y0 * W_ + x0 + pxl;
            #pragma unroll
            for (int hrow = 0; hrow < 2; hrow++) {
                const int co = mt * 16 + g + hrow * 8;
                const float bv = bptr[co];
                float d0 = acc[mt][nt][hrow * 2]     + bv;
                float d1 = acc[mt][nt][hrow * 2 + 1] + bv;
                const size_t off = (size_t)co * HW_ + pbase;
                if (MODE == MODE_MSG) {
                    float2 xv = *(const float2*)(pg[0] + off);
                    float2 ov = make_float2(0.5f * (xv.x + d0), 0.5f * (xv.y + d1));
                    *(float2*)(o0 + off) = ov;
                } else if (MODE == MODE_GATES) {
                    float s0 = 1.f / (1.f + __expf(-d0));
                    float s1 = 1.f / (1.f + __expf(-d1));
                    float2 ov;
                    if (z == 0) {
                        float2 hv = *(const float2*)(g_h + off);
                        ov = make_float2(s0 * hv.x, s1 * hv.y);
                    } else ov = make_float2(s0, s1);
                    *(float2*)(o0 + off) = ov;
                } else {
                    float c0 = tanhf(d0), c1 = tanhf(d1);
                    float2 uv = *(const float2*)(g_u + off);
                    float2 hv = *(const float2*)(g_h + off);
                    float n0 = hv.x + uv.x * (c0 - hv.x);
                    float n1 = hv.y + uv.y * (c1 - hv.y);
                    *(float2*)(g_h + off) = make_float2(n0, n1);
                    *(float2*)(dout + (size_t)t * CHW_ + off) = make_float2(n0, n1);
                }
            }
        }
    }
}

// ---------------- weight repack: OIHW fp32 -> [chunk][co][j] fp16 ----------------
__global__ void repack_k(const float* __restrict__ mw, const float* __restrict__ gw,
                         const float* __restrict__ cw)
{
    int i = blockIdx.x * blockDim.x + threadIdx.x;
    const int S_MSG = 18 * 4096, S_G = 27 * 4096;
    if (i >= S_MSG + 3 * S_G) return;

    const float* src; __half* dst; int CT, coadd = 0;
    if (i < S_MSG)                       { src = mw; dst = g_wh_msg; CT = 128; }
    else if ((i -= S_MSG) < S_G)         { src = gw; dst = g_wh_g0;  CT = 192; }
    else if ((i -= S_G) < S_G)           { src = gw; dst = g_wh_g1;  CT = 192; coadd = 64; }
    else                                 { i -= S_G; src = cw; dst = g_wh_can; CT = 192; }

    int c = i >> 12, rr = i & 4095, co = rr >> 6, j = rr & 63;
    int gpt = CT / 64;
    int tap = c / gpt, cig = c % gpt;
    int dy = tap / 3, dx = tap % 3, ci = cig * 64 + j;
    float v = src[(((size_t)(co + coadd) * CT + ci) * 3 + dy) * 3 + dx];
    dst[i] = __float2half(v);
}

__global__ void zero_h_k()
{
    int i = blockIdx.x * blockDim.x + threadIdx.x;
    int st = gridDim.x * blockDim.x;
    for (; i < CHW_; i += st) g_h[i] = 0.f;
}

// ---------------- launch ----------------
extern "C" void kernel_launch(void* const* d_in, const int* in_sizes, int n_in,
                              void* d_out, int out_size)
{
    const float* x  = (const float*)d_in[0];
    const float* mw = (const float*)d_in[1];
    const float* mb = (const float*)d_in[2];
    const float* gw = (const float*)d_in[3];
    const float* gb = (const float*)d_in[4];
    const float* cw = (const float*)d_in[5];
    const float* cb = (const float*)d_in[6];
    float* out = (float*)d_out;

    cudaFuncSetAttribute(convmma_k<128, MODE_MSG>,   cudaFuncAttributeMaxDynamicSharedMemorySize, SMEM_TOTAL);
    cudaFuncSetAttribute(convmma_k<192, MODE_GATES>, cudaFuncAttributeMaxDynamicSharedMemorySize, SMEM_TOTAL);
    cudaFuncSetAttribute(convmma_k<192, MODE_CAN>,   cudaFuncAttributeMaxDynamicSharedMemorySize, SMEM_TOTAL);

    const int tot = 18 * 4096 + 3 * 27 * 4096;
    repack_k<<<(tot + 255) / 256, 256>>>(mw, gw, cw);
    zero_h_k<<<592, 256>>>();

    // message conv + agg, all 4 batches
    convmma_k<128, MODE_MSG><<<dim3(3, 200, 4), 256, SMEM_TOTAL>>>(x, mb, nullptr, 0);

    // ConvGRU scan over the 4 "sequence" elements
    for (int t = 0; t < 4; t++) {
        convmma_k<192, MODE_GATES><<<dim3(3, 200, 2), 256, SMEM_TOTAL>>>(x, gb, nullptr, t);
        convmma_k<192, MODE_CAN  ><<<dim3(3, 200, 1), 256, SMEM_TOTAL>>>(x, cb, out, t);
    }
}

// round 13
// speedup vs baseline: 5.3127x; 1.6848x over previous
#include <cuda_runtime.h>
#include <cuda_fp16.h>
#include <math.h>
#include <stdint.h>

#define H_ 200
#define W_ 352
#define HW_ (H_*W_)
#define CHW_ (64*HW_)
#define HWC_ ((size_t)HW_*64)

// ---------------- scratch (static device memory; no allocations) ----------------
__device__ __align__(16) float g_h [CHW_];     // GRU state, fp32 NCHW
__device__ __align__(16) float g_u [CHW_];     // update gate, fp32 NCHW
// channel-last fp16 conv operands
__device__ __align__(16) __half g_xh  [8*HW_*64];   // x both agents/batches [n][HW][64]
__device__ __align__(16) __half g_aggh[4*HW_*64];   // agg per batch [b][HW][64]
__device__ __align__(16) __half g_hh  [HW_*64];     // h conv copy
__device__ __align__(16) __half g_rhh [HW_*64];     // reset*h conv copy
// fp16 weights, layout [chunk][co 64][j 64], chunk = tap*GPT + cig
__device__ __align__(16) __half g_wh_msg[18*64*64];
__device__ __align__(16) __half g_wh_g0 [27*64*64];
__device__ __align__(16) __half g_wh_g1 [27*64*64];
__device__ __align__(16) __half g_wh_can[27*64*64];

// ---------------- helpers ----------------
__device__ __forceinline__ uint32_t smem_u32(const void* p) {
    uint32_t a;
    asm("{ .reg .u64 t; cvta.to.shared.u64 t, %1; cvt.u32.u64 %0, t; }" : "=r"(a) : "l"(p));
    return a;
}
#define SW128(o) ((o) ^ (((o) >> 3) & 0x70))

#define LDSM4(R, A) \
    asm volatile("ldmatrix.sync.aligned.m8n8.x4.shared.b16 {%0,%1,%2,%3}, [%4];" \
        : "=r"((R)[0]), "=r"((R)[1]), "=r"((R)[2]), "=r"((R)[3]) : "r"(A))

#define MMA16816H(C, A, B0, B1) \
    asm volatile("mma.sync.aligned.m16n8k16.row.col.f32.f16.f16.f32 " \
        "{%0,%1,%2,%3},{%4,%5,%6,%7},{%8,%9},{%0,%1,%2,%3};" \
        : "+f"((C)[0]), "+f"((C)[1]), "+f"((C)[2]), "+f"((C)[3]) \
        : "r"((A)[0]), "r"((A)[1]), "r"((A)[2]), "r"((A)[3]), "r"(B0), "r"(B1))

#define CPA16(d, s, sz) \
    asm volatile("cp.async.ca.shared.global [%0], [%1], 16, %2;" \
        :: "r"(d), "l"(__cvta_generic_to_global(s)), "r"(sz) : "memory")
#define CPA16F(d, s) \
    asm volatile("cp.async.ca.shared.global [%0], [%1], 16;" \
        :: "r"(d), "l"(__cvta_generic_to_global(s)) : "memory")
#define CPA_COMMIT() asm volatile("cp.async.commit_group;" ::: "memory")
#define CPA_WAIT1()  asm volatile("cp.async.wait_group 1;" ::: "memory")
#define CPA_WAIT0()  asm volatile("cp.async.wait_group 0;" ::: "memory")

enum { MODE_MSG = 0, MODE_GATES = 1, MODE_CAN = 2 };

// smem layout (dynamic):
//  [1024]   W[buf]: 3 tap-chunks x 8KB = 24576 each buf   (co 64 x 128B, SW128)
//  [50176]  X[buf]: 136 rows x 128B = 17408 each buf      (px-halo x 64ci fp16, SW128)
#define OFF_W 1024
#define OFF_X 50176
#define SMEM_TOTAL (50176 + 2*17408)

// ---------------- tensor-core conv3x3 (fp16 mma.sync, dx-shared staging) ----------------
// Tile: M=64 co x 128 px along W (x-tiles {0,128,224}); one H row (y0).
// Outer loop over groups (dy, cig); each group stages a 136-px halo panel once,
// the 3 dx taps read it as row-shifted ldmatrix views.
// Tiles 1/2 overlap x [224,256): bx=2 computes all, writes only px >= 32.
template<int GPT, int MODE>
__global__ void __launch_bounds__(256, 2)
convmma_k(const float* __restrict__ xin, const float* __restrict__ bias,
          float* __restrict__ dout, int t)
{
    extern __shared__ char smem[];
    const uint32_t sbase = smem_u32(smem);
    const int tid = threadIdx.x, wid = tid >> 5, lid = tid & 31;
    const int bx = blockIdx.x, y0 = blockIdx.y, z = blockIdx.z;
    const int x0 = (bx == 2) ? 224 : bx * 128;
    const int pxmin = (bx == 2) ? 32 : 0;
    const int NG = 3 * GPT;

    const __half* pg[3];
    const __half* wb;
    const float* bptr = bias;
    if (MODE == MODE_MSG) {
        pg[0] = g_xh + (size_t)z * HWC_;
        pg[1] = g_xh + (size_t)(4 + z) * HWC_;
        pg[2] = nullptr;
        wb = g_wh_msg;
    } else if (MODE == MODE_GATES) {
        pg[0] = g_xh + (size_t)t * HWC_;
        pg[1] = g_aggh + (size_t)t * HWC_;
        pg[2] = g_hh;
        wb = z ? g_wh_g1 : g_wh_g0;
        bptr = bias + z * 64;
    } else {
        pg[0] = g_xh + (size_t)t * HWC_;
        pg[1] = g_aggh + (size_t)t * HWC_;
        pg[2] = g_rhh;
        wb = g_wh_can;
    }

    // lane constants for ldmatrix addressing
    const int r8 = lid & 7, seg = lid >> 3;
    const uint32_t arow = (uint32_t)(((seg & 1) * 8 + r8) * 128);
    const int akb = seg >> 1;
    const int brow_base = wid * 16 + (seg >> 1) * 8 + r8;   // px row (dx added later)
    const int bkh = seg & 1;

    float acc[4][2][4];
    #pragma unroll
    for (int mt = 0; mt < 4; mt++)
        #pragma unroll
        for (int nt = 0; nt < 2; nt++)
            #pragma unroll
            for (int i = 0; i < 4; i++) acc[mt][nt][i] = 0.f;

    auto issue = [&](int g) {
        const int dy = g / GPT, cig = g % GPT, buf = g & 1;
        const int srow = y0 + dy - 1;
        const bool vy = (unsigned)srow < (unsigned)H_;
        const __half* xp = pg[cig] + (size_t)(vy ? srow : 0) * W_ * 64;
        const uint32_t Xb = sbase + OFF_X + buf * 17408;
        #pragma unroll
        for (int i = 0; i < 5; i++) {
            int task = tid + 256 * i;               // 1088 tasks = 136 px x 8 c16
            if (task < 1088) {
                int px = task >> 3, c16 = task & 7;
                int xg = x0 - 1 + px;
                bool v = vy && (unsigned)xg < (unsigned)W_;
                const __half* s = xp + (size_t)(v ? xg : 0) * 64 + c16 * 8;
                uint32_t d = Xb + SW128((uint32_t)(px * 128 + c16 * 16));
                CPA16(d, s, v ? 16 : 0);
            }
        }
        const uint32_t Wb = sbase + OFF_W + buf * 24576;
        #pragma unroll
        for (int i = 0; i < 6; i++) {
            int task = tid + 256 * i;               // 1536 tasks = 3 chunks x 512
            int dx = task >> 9, idx = task & 511;
            int c = (dy * 3 + dx) * GPT + cig;
            const __half* s = wb + (size_t)c * 4096 + idx * 8;
            uint32_t d = Wb + dx * 8192 + SW128((uint32_t)(idx * 16));
            CPA16F(d, s);
        }
        CPA_COMMIT();
    };

    issue(0);

    for (int g = 0; g < NG; g++) {
        const bool more = (g + 1 < NG);
        if (more) { issue(g + 1); CPA_WAIT1(); }
        else      { CPA_WAIT0(); }
        __syncthreads();

        const int buf = g & 1;
        const uint32_t Wb = sbase + OFF_W + buf * 24576;
        const uint32_t Xb = sbase + OFF_X + buf * 17408;

        #pragma unroll
        for (int dx = 0; dx < 3; dx++) {
            const uint32_t wH = Wb + dx * 8192;
            const int rowb = brow_base + dx;
            const uint32_t bbase = Xb + (uint32_t)(rowb * 128);
            const int r8b = rowb & 7;
            #pragma unroll
            for (int ks = 0; ks < 4; ks++) {
                uint32_t bh[4];
                LDSM4(bh, bbase + ((uint32_t)((ks * 2 + bkh) ^ r8b) << 4));
                const uint32_t aoff = arow + ((uint32_t)((ks * 2 + akb) ^ r8) << 4);
                #pragma unroll
                for (int mt = 0; mt < 4; mt++) {
                    uint32_t a[4];
                    LDSM4(a, wH + mt * 2048 + aoff);
                    MMA16816H(acc[mt][0], a, bh[0], bh[1]);
                    MMA16816H(acc[mt][1], a, bh[2], bh[3]);
                }
            }
        }
        __syncthreads();
    }

    // ---------------- epilogue: acc (co x pixel) -> fused GRU math ----------------
    const int g = lid >> 2, tg = lid & 3;
    #pragma unroll
    for (int mt = 0; mt < 4; mt++) {
        #pragma unroll
        for (int nt = 0; nt < 2; nt++) {
            const int pxl = wid * 16 + nt * 8 + tg * 2;
            if (pxl < pxmin) continue;
            const size_t pbase = (size_t)y0 * W_ + x0 + pxl;     // NCHW pixel index
            const size_t clbase = pbase * 64;                    // channel-last base
            #pragma unroll
            for (int hrow = 0; hrow < 2; hrow++) {
                const int co = mt * 16 + g + hrow * 8;
                const float bv = bptr[co];
                float d0 = acc[mt][nt][hrow * 2]     + bv;
                float d1 = acc[mt][nt][hrow * 2 + 1] + bv;
                const size_t off = (size_t)co * HW_ + pbase;     // NCHW offset
                if (MODE == MODE_MSG) {
                    const float* xsrc = xin + (size_t)z * CHW_;
                    float a0 = 0.5f * (xsrc[off] + d0);
                    float a1 = 0.5f * (xsrc[off + 1] + d1);
                    __half* o = g_aggh + (size_t)z * HWC_ + clbase + co;
                    o[0]  = __float2half(a0);
                    o[64] = __float2half(a1);
                } else if (MODE == MODE_GATES) {
                    float s0 = 1.f / (1.f + __expf(-d0));
                    float s1 = 1.f / (1.f + __expf(-d1));
                    if (z == 0) {
                        float2 hv = *(const float2*)(g_h + off);
                        g_rhh[clbase + co]      = __float2half(s0 * hv.x);
                        g_rhh[clbase + 64 + co] = __float2half(s1 * hv.y);
                    } else {
                        *(float2*)(g_u + off) = make_float2(s0, s1);
                    }
                } else {
                    float c0 = tanhf(d0), c1 = tanhf(d1);
                    float2 uv = *(const float2*)(g_u + off);
                    float2 hv = *(const float2*)(g_h + off);
                    float n0 = hv.x + uv.x * (c0 - hv.x);
                    float n1 = hv.y + uv.y * (c1 - hv.y);
                    *(float2*)(g_h + off) = make_float2(n0, n1);
                    g_hh[clbase + co]      = __float2half(n0);
                    g_hh[clbase + 64 + co] = __float2half(n1);
                    *(float2*)(dout + (size_t)t * CHW_ + off) = make_float2(n0, n1);
                }
            }
        }
    }
}

// ---------------- x pre-convert: fp32 NCHW -> fp16 channel-last [n][HW][64] ----------------
__global__ void xcvt_k(const float* __restrict__ x)
{
    __shared__ __half tile[64][72];
    const int n = blockIdx.y;               // 0..7 (agent*4+batch)
    const int p0 = blockIdx.x * 64;         // HW_ = 70400 = 1100*64
    const int tid = threadIdx.x;
    #pragma unroll
    for (int i = 0; i < 16; i++) {
        int task = tid + 256 * i;           // 4096 = 64ci x 64px
        int ci = task >> 6, px = task & 63;
        tile[px][ci] = __float2half(x[(size_t)n * CHW_ + (size_t)ci * HW_ + p0 + px]);
    }
    __syncthreads();
    #pragma unroll
    for (int i = 0; i < 16; i++) {
        int task = tid + 256 * i;
        int px = task >> 6, ci = task & 63;
        g_xh[(size_t)n * HWC_ + (size_t)(p0 + px) * 64 + ci] = tile[px][ci];
    }
}

// ---------------- weight repack: OIHW fp32 -> [chunk][co][j] fp16 ----------------
__global__ void repack_k(const float* __restrict__ mw, const float* __restrict__ gw,
                         const float* __restrict__ cw)
{
    int i = blockIdx.x * blockDim.x + threadIdx.x;
    const int S_MSG = 18 * 4096, S_G = 27 * 4096;
    if (i >= S_MSG + 3 * S_G) return;

    const float* src; __half* dst; int CT, coadd = 0;
    if (i < S_MSG)                       { src = mw; dst = g_wh_msg; CT = 128; }
    else if ((i -= S_MSG) < S_G)         { src = gw; dst = g_wh_g0;  CT = 192; }
    else if ((i -= S_G) < S_G)           { src = gw; dst = g_wh_g1;  CT = 192; coadd = 64; }
    else                                 { i -= S_G; src = cw; dst = g_wh_can; CT = 192; }

    int c = i >> 12, rr = i & 4095, co = rr >> 6, j = rr & 63;
    int gpt = CT / 64;
    int tap = c / gpt, cig = c % gpt;
    int dy = tap / 3, dx = tap % 3, ci = cig * 64 + j;
    float v = src[(((size_t)(co + coadd) * CT + ci) * 3 + dy) * 3 + dx];
    dst[i] = __float2half(v);
}

__global__ void zero_h_k()
{
    int i = blockIdx.x * blockDim.x + threadIdx.x;
    int st = gridDim.x * blockDim.x;
    for (; i < CHW_; i += st) { g_h[i] = 0.f; g_hh[i] = __float2half(0.f); }
}

// ---------------- launch ----------------
extern "C" void kernel_launch(void* const* d_in, const int* in_sizes, int n_in,
                              void* d_out, int out_size)
{
    const float* x  = (const float*)d_in[0];
    const float* mw = (const float*)d_in[1];
    const float* mb = (const float*)d_in[2];
    const float* gw = (const float*)d_in[3];
    const float* gb = (const float*)d_in[4];
    const float* cw = (const float*)d_in[5];
    const float* cb = (const float*)d_in[6];
    float* out = (float*)d_out;

    cudaFuncSetAttribute(convmma_k<2, MODE_MSG>,   cudaFuncAttributeMaxDynamicSharedMemorySize, SMEM_TOTAL);
    cudaFuncSetAttribute(convmma_k<3, MODE_GATES>, cudaFuncAttributeMaxDynamicSharedMemorySize, SMEM_TOTAL);
    cudaFuncSetAttribute(convmma_k<3, MODE_CAN>,   cudaFuncAttributeMaxDynamicSharedMemorySize, SMEM_TOTAL);

    const int tot = 18 * 4096 + 3 * 27 * 4096;
    repack_k<<<(tot + 255) / 256, 256>>>(mw, gw, cw);
    xcvt_k<<<dim3(1100, 8), 256>>>(x);
    zero_h_k<<<592, 256>>>();

    // message conv + agg, all 4 batches
    convmma_k<2, MODE_MSG><<<dim3(3, 200, 4), 256, SMEM_TOTAL>>>(x, mb, nullptr, 0);

    // ConvGRU scan over the 4 "sequence" elements
    for (int t = 0; t < 4; t++) {
        convmma_k<3, MODE_GATES><<<dim3(3, 200, 2), 256, SMEM_TOTAL>>>(x, gb, nullptr, t);
        convmma_k<3, MODE_CAN  ><<<dim3(3, 200, 1), 256, SMEM_TOTAL>>>(x, cb, out, t);
    }
}